// round 6
// baseline (speedup 1.0000x reference)
#include <cuda_runtime.h>
#include <cstdint>

// Problem dims (fixed for this problem instance)
#define B_DIM 32
#define T_DIM 2048
#define I_DIM 256            // K
#define H_DIM 512
#define M_DIM (B_DIM * T_DIM)   // 65536

#define ALPHA_MIN_F 0.8187307530779818f   // exp(-1/5)
#define ALPHA_MAX_F 0.9607894391523232f   // exp(-1/25)

// Scratch: pre-scaled projection  g_wx[m,h] = (1-alpha_h) * (x @ W^T)[m,h]
__device__ float g_wx[(size_t)M_DIM * H_DIM];

// ===========================================================================
// 3xTF32 mma.sync GEMM  (portable sm_80+ path; compute_103-legal)
//   wx[m,h] = sum_k x[m,k] * W[h,k]
//   x = xhi + xlo (13-bit split, lo rounded to tf32); product approximated by
//   xhi*whi + xhi*wlo + xlo*whi accumulated in fp32.
// CTA tile 128(m) x 128(h), BK=16, 16 stages, 256 threads (8 warps).
// Warp tile 64(m) x 32(h): 4 m16-tiles x 4 n8-tiles, 48 mma per k8-step.
// smem: 4 planes, k-major [BK][PM=132] floats -> fragment LDS conflict-free
// and affine addresses (LDS [R+imm], no index math in the hot loop).
// ===========================================================================
#define PM 132
#define BK 16
#define NSTAGE (I_DIM / BK)     // 16
#define PLANE (BK * PM)         // 2112 u32 per plane

__device__ __forceinline__ void mma_tf32(float c[4], const uint32_t a[4],
                                         const uint32_t b[2]) {
    asm volatile(
        "mma.sync.aligned.m16n8k8.row.col.f32.tf32.tf32.f32 "
        "{%0,%1,%2,%3}, {%4,%5,%6,%7}, {%8,%9}, {%0,%1,%2,%3};"
        : "+f"(c[0]), "+f"(c[1]), "+f"(c[2]), "+f"(c[3])
        : "r"(a[0]), "r"(a[1]), "r"(a[2]), "r"(a[3]), "r"(b[0]), "r"(b[1]));
}

__device__ __forceinline__ void split1(float x, uint32_t& hi, uint32_t& lo) {
    hi = __float_as_uint(x) & 0xFFFFE000u;          // top 10 mantissa bits (tf32-exact)
    float l = x - __uint_as_float(hi);
    asm("cvt.rna.tf32.f32 %0, %1;" : "=r"(lo) : "f"(l));   // round residual to tf32
}

__device__ __forceinline__ void store4(uint32_t* __restrict__ HI,
                                       uint32_t* __restrict__ LO,
                                       int k0, int row, float4 v) {
    uint32_t h, l;
    split1(v.x, h, l); HI[(k0 + 0) * PM + row] = h; LO[(k0 + 0) * PM + row] = l;
    split1(v.y, h, l); HI[(k0 + 1) * PM + row] = h; LO[(k0 + 1) * PM + row] = l;
    split1(v.z, h, l); HI[(k0 + 2) * PM + row] = h; LO[(k0 + 2) * PM + row] = l;
    split1(v.w, h, l); HI[(k0 + 3) * PM + row] = h; LO[(k0 + 3) * PM + row] = l;
}

__global__ __launch_bounds__(256, 2) void lif_mma_gemm(
    const float* __restrict__ X,
    const float* __restrict__ Wm,
    const float* __restrict__ alpha_in)
{
    __shared__ uint32_t AHI[PLANE], ALO[PLANE], BHI[PLANE], BLO[PLANE];

    const int tid  = threadIdx.x;
    const int wid  = tid >> 5;
    const int lane = tid & 31;
    const int wm = wid & 1;          // m half (64 rows each)
    const int wn = wid >> 1;         // n quarter (32 cols each)
    const int gr = lane >> 2;        // 0..7
    const int tc = lane & 3;         // 0..3

    const int m0 = (blockIdx.x >> 2) * 128;
    const int h0 = (blockIdx.x & 3) * 128;

    // GMEM staging: thread -> row = tid>>1 (0..127), k-half = (tid&1)*8
    const int lrow = tid >> 1;
    const int lkh  = (tid & 1) * 8;
    const float* Ap = X  + (size_t)(m0 + lrow) * I_DIM + lkh;
    const float* Bp = Wm + (size_t)(h0 + lrow) * I_DIM + lkh;

    float acc[4][4][4];
    #pragma unroll
    for (int mt = 0; mt < 4; mt++)
        #pragma unroll
        for (int nt = 0; nt < 4; nt++)
            #pragma unroll
            for (int r = 0; r < 4; r++)
                acc[mt][nt][r] = 0.0f;

    // Fragment base indices in the k-major planes (affine; offsets are imms)
    int abase[4], bbase[4];
    #pragma unroll
    for (int mt = 0; mt < 4; mt++)
        abase[mt] = tc * PM + wm * 64 + mt * 16 + gr;
    #pragma unroll
    for (int nt = 0; nt < 4; nt++)
        bbase[nt] = tc * PM + wn * 32 + nt * 8 + gr;

    // Prologue: stage 0
    float4 ra0 = *(const float4*)(Ap);
    float4 ra1 = *(const float4*)(Ap + 4);
    float4 rb0 = *(const float4*)(Bp);
    float4 rb1 = *(const float4*)(Bp + 4);
    store4(AHI, ALO, lkh, lrow, ra0);
    store4(AHI, ALO, lkh + 4, lrow, ra1);
    store4(BHI, BLO, lkh, lrow, rb0);
    store4(BHI, BLO, lkh + 4, lrow, rb1);
    __syncthreads();

    #pragma unroll 1
    for (int s = 0; s < NSTAGE; s++) {
        // Prefetch next stage (LDG latency hidden behind the mma block)
        if (s + 1 < NSTAGE) {
            const float* An = Ap + (s + 1) * BK;
            const float* Bn = Bp + (s + 1) * BK;
            ra0 = *(const float4*)(An);
            ra1 = *(const float4*)(An + 4);
            rb0 = *(const float4*)(Bn);
            rb1 = *(const float4*)(Bn + 4);
        }

        // Two k8 steps over this stage
        #pragma unroll
        for (int ks = 0; ks < 2; ks++) {
            const int ko = ks * 8 * PM;   // 0 or 1056

            uint32_t bh[4][2], bl[4][2];
            #pragma unroll
            for (int nt = 0; nt < 4; nt++) {
                const int b0i = bbase[nt] + ko;
                bh[nt][0] = BHI[b0i];
                bh[nt][1] = BHI[b0i + 4 * PM];
                bl[nt][0] = BLO[b0i];
                bl[nt][1] = BLO[b0i + 4 * PM];
            }

            #pragma unroll
            for (int mt = 0; mt < 4; mt++) {
                const int a0i = abase[mt] + ko;
                uint32_t ah[4], al[4];
                ah[0] = AHI[a0i];             ah[1] = AHI[a0i + 8];
                ah[2] = AHI[a0i + 4 * PM];    ah[3] = AHI[a0i + 4 * PM + 8];
                al[0] = ALO[a0i];             al[1] = ALO[a0i + 8];
                al[2] = ALO[a0i + 4 * PM];    al[3] = ALO[a0i + 4 * PM + 8];

                #pragma unroll
                for (int nt = 0; nt < 4; nt++) {
                    mma_tf32(acc[mt][nt], ah, bh[nt]);   // hi*hi
                    mma_tf32(acc[mt][nt], ah, bl[nt]);   // hi*lo
                    mma_tf32(acc[mt][nt], al, bh[nt]);   // lo*hi
                }
            }
        }
        __syncthreads();

        if (s + 1 < NSTAGE) {
            store4(AHI, ALO, lkh, lrow, ra0);
            store4(AHI, ALO, lkh + 4, lrow, ra1);
            store4(BHI, BLO, lkh, lrow, rb0);
            store4(BHI, BLO, lkh + 4, lrow, rb1);
            __syncthreads();
        }
    }

    // Epilogue: scale by bc[h] = 1 - clamp(alpha[h]), store (float2, coalesced
    // 32B sectors: 4 lanes x 8B contiguous per (mt,nt) quad-group)
    float bc[4][2];
    #pragma unroll
    for (int nt = 0; nt < 4; nt++) {
        #pragma unroll
        for (int c = 0; c < 2; c++) {
            int h = h0 + wn * 32 + nt * 8 + tc * 2 + c;
            float a = alpha_in[h];
            a = fminf(fmaxf(a, ALPHA_MIN_F), ALPHA_MAX_F);
            bc[nt][c] = 1.0f - a;
        }
    }

    const int hcol = h0 + wn * 32 + tc * 2;
    #pragma unroll
    for (int mt = 0; mt < 4; mt++) {
        int m = m0 + wm * 64 + mt * 16 + gr;
        float* r0 = &g_wx[(size_t)m * H_DIM + hcol];
        float* r1 = &g_wx[(size_t)(m + 8) * H_DIM + hcol];
        #pragma unroll
        for (int nt = 0; nt < 4; nt++) {
            float2 v0 = make_float2(acc[mt][nt][0] * bc[nt][0],
                                    acc[mt][nt][1] * bc[nt][1]);
            float2 v1 = make_float2(acc[mt][nt][2] * bc[nt][0],
                                    acc[mt][nt][3] * bc[nt][1]);
            *(float2*)(r0 + nt * 8) = v0;
            *(float2*)(r1 + nt * 8) = v1;
        }
    }
}

// ===========================================================================
// Scan (unchanged): one thread per (b,h) chain, distance-3 prefetch,
// predicate-form recurrence. At its structural latency-BW cap (~3 TB/s).
// ===========================================================================
__global__ __launch_bounds__(64) void lif_scan_kernel(
    const float* __restrict__ alpha_in,
    const float* __restrict__ u0,
    const float* __restrict__ s0,
    float* __restrict__ out)
{
    const int b = blockIdx.x >> 3;
    const int h = (blockIdx.x & 7) * 64 + threadIdx.x;

    float a = alpha_in[h];
    a = fminf(fmaxf(a, ALPHA_MIN_F), ALPHA_MAX_F);

    float u = u0[b * H_DIM + h];
    float s = s0[b * H_DIM + h];

    const float* __restrict__ wx = g_wx + (size_t)b * T_DIM * H_DIM + h;
    float* __restrict__ o = out + (size_t)b * T_DIM * H_DIM + h;

    constexpr int U = 16;
    constexpr int NCH = T_DIM / U;
    float buf[4][U];

    #pragma unroll
    for (int c0 = 0; c0 < 3; c0++) {
        const float* p = wx + (size_t)c0 * U * H_DIM;
        #pragma unroll
        for (int i = 0; i < U; i++)
            buf[c0][i] = p[(size_t)i * H_DIM];
    }

    {
        const float* p = wx + (size_t)3 * U * H_DIM;
        #pragma unroll
        for (int i = 0; i < U; i++)
            buf[3][i] = p[(size_t)i * H_DIM];

        #pragma unroll
        for (int i = 0; i < U; i++) {
            u = a * (u - s) + buf[0][i];            // buf already = bc*wx
            s = (u > 1.0f) ? 1.0f : 0.0f;
            o[(size_t)i * H_DIM] = s;
        }
    }
    bool pr = (s != 0.0f);

    #pragma unroll 4
    for (int c = 1; c < NCH; c++) {
        if (c + 3 < NCH) {
            const float* p = wx + (size_t)(c + 3) * U * H_DIM;
            #pragma unroll
            for (int i = 0; i < U; i++)
                buf[(c + 3) & 3][i] = p[(size_t)i * H_DIM];
        }
        float* po = o + (size_t)c * U * H_DIM;
        #pragma unroll
        for (int i = 0; i < U; i++) {
            float w  = buf[c & 3][i];
            float d  = u - 1.0f;
            float um = pr ? d : u;
            u  = fmaf(a, um, w);
            pr = (u > 1.0f);
            po[(size_t)i * H_DIM] = pr ? 1.0f : 0.0f;
        }
    }
}

// ---------------------------------------------------------------------------
// Launch
// ---------------------------------------------------------------------------
extern "C" void kernel_launch(void* const* d_in, const int* in_sizes, int n_in,
                              void* d_out, int out_size)
{
    const float* x     = (const float*)d_in[0];  // [B, T, I]
    const float* W     = (const float*)d_in[1];  // [H, I]
    const float* alpha = (const float*)d_in[2];  // [H]
    const float* u0    = (const float*)d_in[3];  // [B, H]
    const float* s0    = (const float*)d_in[4];  // [B, H]
    float* out = (float*)d_out;                  // [B, T, H]

    (void)in_sizes; (void)n_in; (void)out_size;

    // GEMM: 512 m-tiles x 4 h-tiles = 2048 CTAs of 256 threads
    lif_mma_gemm<<<2048, 256>>>(x, W, alpha);

    // Scan: 32 batches x 8 h-chunks = 256 CTAs of 64 threads
    lif_scan_kernel<<<B_DIM * 8, 64>>>(alpha, u0, s0, out);
}